// round 2
// baseline (speedup 1.0000x reference)
#include <cuda_runtime.h>

#define NN   4096
#define INF  256
#define OUTF 64
#define H    8

// ---------------- device scratch (no allocs allowed) ----------------
__device__ float g_h [H*NN*OUTF];          // projected features, fp32  (8 MB)
__device__ float g_hp[H*NN*OUTF];          // per-head attention output (8 MB)
__device__ float g_src[H*NN], g_dst[H*NN];
__device__ float g_E1[H*NN], g_E2[H*NN];   // exp(src), exp(0.2*src)
__device__ float g_F1[H*NN], g_F2[H*NN];   // exp(dst), exp(0.2*dst)
__device__ unsigned g_adj[NN*(NN/32)];     // packed adjacency bitmask (2 MB)

// ---------------- K1: h[hd][n][o] = sum_k x[n][k] * W[hd][k][o] ----------------
// 128 blocks of 32 rows, 512 threads: thread t -> (head = t>>6, o = t&63), 32 row accs.
__global__ void __launch_bounds__(512) k_gemm(const float* __restrict__ x,
                                              const float* __restrict__ W) {
    __shared__ float4 xs[32][64];          // x tile [32 rows][256 k] as float4
    const int t  = threadIdx.x;
    const int n0 = blockIdx.x * 32;
    const float4* x4 = reinterpret_cast<const float4*>(x) + (size_t)n0 * 64;
    for (int i = t; i < 32 * 64; i += 512) {
        int r = i >> 6, c = i & 63;
        xs[r][c] = x4[r * 64 + c];
    }
    __syncthreads();

    const int hd = t >> 6, o = t & 63;
    const float* Wp = W + hd * INF * OUTF + o;
    float acc[32];
#pragma unroll
    for (int r = 0; r < 32; r++) acc[r] = 0.f;

    for (int k4 = 0; k4 < 64; k4++) {
        float w0 = Wp[(4 * k4 + 0) * OUTF];
        float w1 = Wp[(4 * k4 + 1) * OUTF];
        float w2 = Wp[(4 * k4 + 2) * OUTF];
        float w3 = Wp[(4 * k4 + 3) * OUTF];
#pragma unroll
        for (int r = 0; r < 32; r++) {
            float4 xv = xs[r][k4];
            acc[r] += xv.x * w0 + xv.y * w1 + xv.z * w2 + xv.w * w3;
        }
    }
#pragma unroll
    for (int r = 0; r < 32; r++)
        g_h[((size_t)hd * NN + n0 + r) * OUTF + o] = acc[r];
}

// ---------------- K2: src/dst dot products + factored exps ----------------
// one warp per (head, node)
__global__ void __launch_bounds__(256) k_attvec(const float* __restrict__ a) {
    const int warp = (blockIdx.x * blockDim.x + threadIdx.x) >> 5;
    const int lane = threadIdx.x & 31;
    if (warp >= H * NN) return;
    const int hd = warp >> 12;                       // / 4096
    const float* hv = g_h + (size_t)warp * OUTF;
    const float* ap = a + hd * (2 * OUTF);
    float v0 = hv[lane], v1 = hv[32 + lane];
    float s = v0 * ap[lane]      + v1 * ap[32 + lane];
    float d = v0 * ap[64 + lane] + v1 * ap[96 + lane];
#pragma unroll
    for (int off = 16; off; off >>= 1) {
        s += __shfl_xor_sync(~0u, s, off);
        d += __shfl_xor_sync(~0u, d, off);
    }
    if (lane == 0) {
        g_src[warp] = s;  g_E1[warp] = __expf(s);  g_E2[warp] = __expf(0.2f * s);
        g_dst[warp] = d;  g_F1[warp] = __expf(d);  g_F2[warp] = __expf(0.2f * d);
    }
}

// ---------------- K3: pack adjacency to bitmask ----------------
__global__ void __launch_bounds__(256) k_pack(const int* __restrict__ adj) {
    const int warp = (blockIdx.x * blockDim.x + threadIdx.x) >> 5;
    const int lane = threadIdx.x & 31;
    const int base = warp * 32;                      // 32 words per warp
#pragma unroll 4
    for (int i = 0; i < 32; i++) {
        int wb = base + i;                           // word index = n*128 + wd
        unsigned m = __ballot_sync(~0u, adj[(size_t)wb * 32 + lane] != 0);
        if (lane == 0) g_adj[wb] = m;
    }
}

// ---------------- K4: fused masked-softmax attention (fp32) ----------------
// grid (32, 8): blockIdx.x = 128-row tile, blockIdx.y = head. 256 threads.
// thread t -> rows {2*(t>>2), 2*(t>>2)+1}, cols [16*(t&3), 16*(t&3)+16)
__global__ void __launch_bounds__(256) k_attn() {
    __shared__ float4  hs[32][16];        // h tile: 32 m-rows x 64 cols
    __shared__ float   nums[32][128];     // weights: [m][row]
    __shared__ float   srow[128], e1r[128], e2r[128];
    __shared__ unsigned adjw[128];
    __shared__ float   ds[32], f1s[32], f2s[32];

    const int t  = threadIdx.x;
    const int hd = blockIdx.y;
    const int n0 = blockIdx.x * 128;

    if (t < 128) {
        int idx = hd * NN + n0 + t;
        srow[t] = g_src[idx]; e1r[t] = g_E1[idx]; e2r[t] = g_E2[idx];
    }

    const int r2 = t >> 2;                 // 0..63
    const int g4 = t & 3;                  // col group (4 float4 each)
    const int row0 = 2 * r2, row1 = row0 + 1;

    float4 ac0[4], ac1[4];
#pragma unroll
    for (int q = 0; q < 4; q++) {
        ac0[q] = make_float4(0.f, 0.f, 0.f, 0.f);
        ac1[q] = make_float4(0.f, 0.f, 0.f, 0.f);
    }
    float Z0 = 0.f, Z1 = 0.f;

    const float4* h4 = reinterpret_cast<const float4*>(g_h) + (size_t)hd * NN * 16;

    for (int mc = 0; mc < 128; mc++) {
        const int m0 = mc * 32;
        __syncthreads();                    // protect prev-iter reads / startup
        // phase 1: stage tiles
#pragma unroll
        for (int j = 0; j < 2; j++) {
            int idx = t + 256 * j;
            int m = idx >> 4, c4 = idx & 15;
            hs[m][c4] = h4[(size_t)(m0 + m) * 16 + c4];
        }
        if (t < 32) {
            int idx = hd * NN + m0 + t;
            ds[t] = g_dst[idx]; f1s[t] = g_F1[idx]; f2s[t] = g_F2[idx];
        } else if (t >= 128) {
            adjw[t - 128] = g_adj[(size_t)(n0 + t - 128) * 128 + mc];
        }
        __syncthreads();
        // phase 2: build weights (no per-pair exp!)
#pragma unroll
        for (int i = 0; i < 16; i++) {
            int lin = t + 256 * i;
            int m = lin >> 7, r = lin & 127;
            bool on = (adjw[r] >> m) & 1u;
            float v = (srow[r] + ds[m] >= 0.f) ? e1r[r] * f1s[m]
                                               : e2r[r] * f2s[m];
            nums[m][r] = on ? v : 0.f;
        }
        __syncthreads();
        // phase 3: accumulate P @ h
#pragma unroll
        for (int m = 0; m < 32; m++) {
            float w0 = nums[m][row0];
            float w1 = nums[m][row1];
            Z0 += w0; Z1 += w1;
#pragma unroll
            for (int q = 0; q < 4; q++) {
                float4 hv = hs[m][g4 * 4 + q];
                ac0[q].x += w0 * hv.x; ac0[q].y += w0 * hv.y;
                ac0[q].z += w0 * hv.z; ac0[q].w += w0 * hv.w;
                ac1[q].x += w1 * hv.x; ac1[q].y += w1 * hv.y;
                ac1[q].z += w1 * hv.z; ac1[q].w += w1 * hv.w;
            }
        }
    }

    const float iz0 = 1.f / Z0, iz1 = 1.f / Z1;
    float4* hp4 = reinterpret_cast<float4*>(g_hp) + (size_t)hd * NN * 16;
#pragma unroll
    for (int q = 0; q < 4; q++) {
        float4 o0 = ac0[q], o1 = ac1[q];
        o0.x *= iz0; o0.y *= iz0; o0.z *= iz0; o0.w *= iz0;
        o1.x *= iz1; o1.y *= iz1; o1.z *= iz1; o1.w *= iz1;
        hp4[(size_t)(n0 + row0) * 16 + g4 * 4 + q] = o0;
        hp4[(size_t)(n0 + row1) * 16 + g4 * 4 + q] = o1;
    }
}

// ---------------- K5: mean over heads + ELU ----------------
__global__ void __launch_bounds__(256) k_final(float* __restrict__ out) {
    const int i = blockIdx.x * 256 + threadIdx.x;   // n*64 + o
    float s = 0.f;
#pragma unroll
    for (int hd = 0; hd < H; hd++) s += g_hp[(size_t)hd * NN * OUTF + i];
    s *= (1.f / H);
    out[i] = (s > 0.f) ? s : (__expf(s) - 1.f);
}

// ---------------- launch ----------------
extern "C" void kernel_launch(void* const* d_in, const int* in_sizes, int n_in,
                              void* d_out, int out_size) {
    const float* x   = (const float*)d_in[0];
    const int*   adj = (const int*)  d_in[1];
    const float* W   = (const float*)d_in[2];
    const float* a   = (const float*)d_in[3];
    float* out = (float*)d_out;

    k_gemm  <<<128, 512>>>(x, W);
    k_attvec<<<(H * NN / 8 + 0), 256>>>(a);      // 4096 blocks, 8 warps each
    k_pack  <<<2048, 256>>>(adj);
    k_attn  <<<dim3(32, 8), 256>>>();
    k_final <<<NN * OUTF / 256, 256>>>(out);
}

// round 5
// speedup vs baseline: 1.1695x; 1.1695x over previous
#include <cuda_runtime.h>

#define NN   4096
#define INF  256
#define OUTF 64
#define H    8

typedef unsigned long long u64;

// ---------------- device scratch (no allocs allowed) ----------------
__device__ float g_h [H*NN*OUTF];          // projected features, fp32  (8 MB)
__device__ float g_hp[H*NN*OUTF];          // per-head attention output (8 MB)
__device__ float g_src[H*NN], g_dst[H*NN];
__device__ float g_E1[H*NN], g_E2[H*NN];   // exp(src), exp(0.2*src)
__device__ float g_F1[H*NN], g_F2[H*NN];   // exp(dst), exp(0.2*dst)
__device__ unsigned g_adj[NN*(NN/32)];     // packed adjacency bitmask (2 MB)

// ---------------- f32x2 packed helpers ----------------
__device__ __forceinline__ u64 pk2(float v) {
    u64 r; asm("mov.b64 %0, {%1, %1};" : "=l"(r) : "f"(v)); return r;
}
__device__ __forceinline__ u64 f2fma(u64 a, u64 b, u64 c) {
    u64 d; asm("fma.rn.f32x2 %0, %1, %2, %3;" : "=l"(d) : "l"(a), "l"(b), "l"(c)); return d;
}
__device__ __forceinline__ u64 f2mul(u64 a, u64 b) {
    u64 d; asm("mul.rn.f32x2 %0, %1, %2;" : "=l"(d) : "l"(a), "l"(b)); return d;
}

// ---------------- K1: h[hd][n][o] = sum_k x[n][k] * W[hd][k][o] ----------------
__global__ void __launch_bounds__(512) k_gemm(const float* __restrict__ x,
                                              const float* __restrict__ W) {
    __shared__ float4 xs[32][64];
    const int t  = threadIdx.x;
    const int n0 = blockIdx.x * 32;
    const float4* x4 = reinterpret_cast<const float4*>(x) + (size_t)n0 * 64;
    for (int i = t; i < 32 * 64; i += 512) {
        int r = i >> 6, c = i & 63;
        xs[r][c] = x4[r * 64 + c];
    }
    __syncthreads();

    const int hd = t >> 6, o = t & 63;
    const float* Wp = W + hd * INF * OUTF + o;
    float acc[32];
#pragma unroll
    for (int r = 0; r < 32; r++) acc[r] = 0.f;

    for (int k4 = 0; k4 < 64; k4++) {
        float w0 = Wp[(4 * k4 + 0) * OUTF];
        float w1 = Wp[(4 * k4 + 1) * OUTF];
        float w2 = Wp[(4 * k4 + 2) * OUTF];
        float w3 = Wp[(4 * k4 + 3) * OUTF];
#pragma unroll
        for (int r = 0; r < 32; r++) {
            float4 xv = xs[r][k4];
            acc[r] += xv.x * w0 + xv.y * w1 + xv.z * w2 + xv.w * w3;
        }
    }
#pragma unroll
    for (int r = 0; r < 32; r++)
        g_h[((size_t)hd * NN + n0 + r) * OUTF + o] = acc[r];
}

// ---------------- K2: src/dst dot products + factored exps ----------------
__global__ void __launch_bounds__(256) k_attvec(const float* __restrict__ a) {
    const int warp = (blockIdx.x * blockDim.x + threadIdx.x) >> 5;
    const int lane = threadIdx.x & 31;
    if (warp >= H * NN) return;
    const int hd = warp >> 12;
    const float* hv = g_h + (size_t)warp * OUTF;
    const float* ap = a + hd * (2 * OUTF);
    float v0 = hv[lane], v1 = hv[32 + lane];
    float s = v0 * ap[lane]      + v1 * ap[32 + lane];
    float d = v0 * ap[64 + lane] + v1 * ap[96 + lane];
#pragma unroll
    for (int off = 16; off; off >>= 1) {
        s += __shfl_xor_sync(~0u, s, off);
        d += __shfl_xor_sync(~0u, d, off);
    }
    if (lane == 0) {
        g_src[warp] = s;  g_E1[warp] = __expf(s);  g_E2[warp] = __expf(0.2f * s);
        g_dst[warp] = d;  g_F1[warp] = __expf(d);  g_F2[warp] = __expf(0.2f * d);
    }
}

// ---------------- K3: pack adjacency to bitmask ----------------
__global__ void __launch_bounds__(256) k_pack(const int* __restrict__ adj) {
    const int warp = (blockIdx.x * blockDim.x + threadIdx.x) >> 5;
    const int lane = threadIdx.x & 31;
    const int base = warp * 32;
#pragma unroll 4
    for (int i = 0; i < 32; i++) {
        int wb = base + i;
        unsigned m = __ballot_sync(~0u, adj[(size_t)wb * 32 + lane] != 0);
        if (lane == 0) g_adj[wb] = m;
    }
}

// ---------------- K4: fused masked-softmax attention (fp32, f32x2 FMA) ----------------
// grid (64, 8): 64-row tile per block, 128 threads.
// weight role:  thread -> row rw = t&63, m-halfgroup mg = (t>>6)*16
// accum role:   thread -> row pair rp = t>>2 (rows 2rp,2rp+1), col group g4 = t&3 (16 cols)
__global__ void __launch_bounds__(128, 6) k_attn() {
    __shared__ __align__(16) ulonglong2 hs2[32][16];   // h tile: 32 m-rows x 64 cols
    __shared__ __align__(16) float nums[32][64];       // weights [m][row]
    __shared__ float dmv[32], f1v[32], f2v[32];

    const int t  = threadIdx.x;
    const int hd = blockIdx.y;
    const int n0 = blockIdx.x * 64;

    // ---- weight-role constants, held in registers for the whole kernel ----
    const int rw = t & 63;
    const int mg = (t >> 6) << 4;                 // 0 or 16
    const int ridx = hd * NN + n0 + rw;
    const float sW  = g_src[ridx];
    const float e1W = g_E1[ridx];
    const float e2W = g_E2[ridx];
    const unsigned* __restrict__ adjrow = g_adj + (size_t)(n0 + rw) * 128;

    // ---- accumulation role ----
    const int rp = t >> 2, g4 = t & 3;
    const int row0 = rp * 2;

    u64 ac0[8], ac1[8];
#pragma unroll
    for (int q = 0; q < 8; q++) { ac0[q] = 0ull; ac1[q] = 0ull; }
    float Z0 = 0.f, Z1 = 0.f;

    const ulonglong2* __restrict__ h4g =
        reinterpret_cast<const ulonglong2*>(g_h) + (size_t)hd * NN * 16;

    for (int mc = 0; mc < 128; mc++) {
        const int m0 = mc * 32;
        __syncthreads();
        // stage h tile (32 x 64 floats = 512 x 16B)
#pragma unroll
        for (int j = 0; j < 4; j++) {
            int i = t + 128 * j;
            hs2[i >> 4][i & 15] = h4g[(size_t)(m0 + (i >> 4)) * 16 + (i & 15)];
        }
        if (t < 32) {
            int idx = hd * NN + m0 + t;
            dmv[t] = g_dst[idx]; f1v[t] = g_F1[idx]; f2v[t] = g_F2[idx];
        }
        const unsigned aw = adjrow[mc];            // L2-resident bitmask
        __syncthreads();

        // weights: each thread does 16 (row, m) pairs, once per pair
#pragma unroll
        for (int j = 0; j < 16; j++) {
            int m = mg + j;
            float d = dmv[m];
            float v = (sW + d >= 0.f) ? e1W * f1v[m] : e2W * f2v[m];
            nums[m][rw] = ((aw >> m) & 1u) ? v : 0.f;
        }
        __syncthreads();

        // accumulate P @ h with packed f32x2 FMAs
#pragma unroll 8
        for (int m = 0; m < 32; m++) {
            float2 w = reinterpret_cast<const float2*>(nums[m])[rp];
            Z0 += w.x; Z1 += w.y;
            u64 w0 = pk2(w.x), w1 = pk2(w.y);
#pragma unroll
            for (int q = 0; q < 4; q++) {
                ulonglong2 hv = hs2[m][g4 * 4 + q];
                ac0[2 * q]     = f2fma(hv.x, w0, ac0[2 * q]);
                ac0[2 * q + 1] = f2fma(hv.y, w0, ac0[2 * q + 1]);
                ac1[2 * q]     = f2fma(hv.x, w1, ac1[2 * q]);
                ac1[2 * q + 1] = f2fma(hv.y, w1, ac1[2 * q + 1]);
            }
        }
    }

    // epilogue: normalize and store (still packed)
    const u64 iz0 = pk2(1.f / Z0), iz1 = pk2(1.f / Z1);
    ulonglong2* o0 = reinterpret_cast<ulonglong2*>(g_hp) +
                     ((size_t)hd * NN + n0 + row0) * 16 + g4 * 4;
    ulonglong2* o1 = o0 + 16;
#pragma unroll
    for (int q = 0; q < 4; q++) {
        o0[q] = make_ulonglong2(f2mul(ac0[2 * q], iz0), f2mul(ac0[2 * q + 1], iz0));
        o1[q] = make_ulonglong2(f2mul(ac1[2 * q], iz1), f2mul(ac1[2 * q + 1], iz1));
    }
}

// ---------------- K5: mean over heads + ELU ----------------
__global__ void __launch_bounds__(256) k_final(float* __restrict__ out) {
    const int i = blockIdx.x * 256 + threadIdx.x;
    float s = 0.f;
#pragma unroll
    for (int hd = 0; hd < H; hd++) s += g_hp[(size_t)hd * NN * OUTF + i];
    s *= (1.f / H);
    out[i] = (s > 0.f) ? s : (__expf(s) - 1.f);
}

// ---------------- launch ----------------
extern "C" void kernel_launch(void* const* d_in, const int* in_sizes, int n_in,
                              void* d_out, int out_size) {
    const float* x   = (const float*)d_in[0];
    const int*   adj = (const int*)  d_in[1];
    const float* W   = (const float*)d_in[2];
    const float* a   = (const float*)d_in[3];
    float* out = (float*)d_out;

    k_gemm  <<<128, 512>>>(x, W);
    k_attvec<<<H * NN / 8, 256>>>(a);
    k_pack  <<<2048, 256>>>(adj);
    k_attn  <<<dim3(64, 8), 128>>>();
    k_final <<<NN * OUTF / 256, 256>>>(out);
}

// round 8
// speedup vs baseline: 1.2234x; 1.0460x over previous
#include <cuda_runtime.h>

#define NN   4096
#define INF  256
#define OUTF 64
#define H    8

typedef unsigned long long u64;

// ---------------- device scratch (no allocs allowed) ----------------
__device__ float  g_h [H*NN*OUTF];         // projected features, fp32  (8 MB)
__device__ float  g_hp[H*NN*OUTF];         // per-head attention output (8 MB)
__device__ float  g_src[H*NN], g_E1[H*NN], g_E2[H*NN];   // row-side factors
__device__ float4 g_mp[H*NN];              // m-side params: (-dst, F1, F2, 0)
__device__ unsigned g_adj[NN*(NN/32)];     // packed adjacency bitmask (2 MB)

// ---------------- f32x2 packed helpers ----------------
__device__ __forceinline__ u64 pk2(float v) {
    u64 r; asm("mov.b64 %0, {%1, %1};" : "=l"(r) : "f"(v)); return r;
}
__device__ __forceinline__ u64 pack2(float x, float y) {
    u64 r; asm("mov.b64 %0, {%1, %2};" : "=l"(r) : "f"(x), "f"(y)); return r;
}
__device__ __forceinline__ u64 f2fma(u64 a, u64 b, u64 c) {
    u64 d; asm("fma.rn.f32x2 %0, %1, %2, %3;" : "=l"(d) : "l"(a), "l"(b), "l"(c)); return d;
}
__device__ __forceinline__ u64 f2add(u64 a, u64 b) {
    u64 d; asm("add.rn.f32x2 %0, %1, %2;" : "=l"(d) : "l"(a), "l"(b)); return d;
}
__device__ __forceinline__ u64 f2mul(u64 a, u64 b) {
    u64 d; asm("mul.rn.f32x2 %0, %1, %2;" : "=l"(d) : "l"(a), "l"(b)); return d;
}
__device__ __forceinline__ void unpack2(u64 v, float& x, float& y) {
    asm("mov.b64 {%0, %1}, %2;" : "=f"(x), "=f"(y) : "l"(v));
}
// ---------------- cp.async helpers ----------------
__device__ __forceinline__ void cpa16(void* dst, const void* src) {
    unsigned ds = (unsigned)__cvta_generic_to_shared(dst);
    asm volatile("cp.async.ca.shared.global [%0], [%1], 16;" :: "r"(ds), "l"(src));
}
__device__ __forceinline__ void cpcommit() { asm volatile("cp.async.commit_group;"); }
__device__ __forceinline__ void cpwait0()  { asm volatile("cp.async.wait_group 0;"); }

// ---------------- K1: h[hd][n][o] = sum_k x[n][k] * W[hd][k][o] ----------------
__global__ void __launch_bounds__(512) k_gemm(const float* __restrict__ x,
                                              const float* __restrict__ W) {
    __shared__ float4 xs[32][64];
    const int t  = threadIdx.x;
    const int n0 = blockIdx.x * 32;
    const float4* x4 = reinterpret_cast<const float4*>(x) + (size_t)n0 * 64;
    for (int i = t; i < 32 * 64; i += 512) {
        int r = i >> 6, c = i & 63;
        xs[r][c] = x4[r * 64 + c];
    }
    __syncthreads();

    const int hd = t >> 6, o = t & 63;
    const float* Wp = W + hd * INF * OUTF + o;
    float acc[32];
#pragma unroll
    for (int r = 0; r < 32; r++) acc[r] = 0.f;

    for (int k4 = 0; k4 < 64; k4++) {
        float w0 = Wp[(4 * k4 + 0) * OUTF];
        float w1 = Wp[(4 * k4 + 1) * OUTF];
        float w2 = Wp[(4 * k4 + 2) * OUTF];
        float w3 = Wp[(4 * k4 + 3) * OUTF];
#pragma unroll
        for (int r = 0; r < 32; r++) {
            float4 xv = xs[r][k4];
            acc[r] += xv.x * w0 + xv.y * w1 + xv.z * w2 + xv.w * w3;
        }
    }
#pragma unroll
    for (int r = 0; r < 32; r++)
        g_h[((size_t)hd * NN + n0 + r) * OUTF + o] = acc[r];
}

// ---------------- K2: src/dst dot products + factored exps ----------------
__global__ void __launch_bounds__(256) k_attvec(const float* __restrict__ a) {
    const int warp = (blockIdx.x * blockDim.x + threadIdx.x) >> 5;
    const int lane = threadIdx.x & 31;
    if (warp >= H * NN) return;
    const int hd = warp >> 12;
    const float* hv = g_h + (size_t)warp * OUTF;
    const float* ap = a + hd * (2 * OUTF);
    float v0 = hv[lane], v1 = hv[32 + lane];
    float s = v0 * ap[lane]      + v1 * ap[32 + lane];
    float d = v0 * ap[64 + lane] + v1 * ap[96 + lane];
#pragma unroll
    for (int off = 16; off; off >>= 1) {
        s += __shfl_xor_sync(~0u, s, off);
        d += __shfl_xor_sync(~0u, d, off);
    }
    if (lane == 0) {
        g_src[warp] = s;  g_E1[warp] = __expf(s);  g_E2[warp] = __expf(0.2f * s);
        g_mp[warp]  = make_float4(-d, __expf(d), __expf(0.2f * d), 0.f);
    }
}

// ---------------- K3: pack adjacency to bitmask ----------------
__global__ void __launch_bounds__(256) k_pack(const int* __restrict__ adj) {
    const int warp = (blockIdx.x * blockDim.x + threadIdx.x) >> 5;
    const int lane = threadIdx.x & 31;
    const int base = warp * 32;
#pragma unroll 4
    for (int i = 0; i < 32; i++) {
        int wb = base + i;
        unsigned m = __ballot_sync(~0u, adj[(size_t)wb * 32 + lane] != 0);
        if (lane == 0) g_adj[wb] = m;
    }
}

// ---------------- K4: fused attention, cp.async double-buffered ----------------
// grid (64, 8): 64-row tile per block, 128 threads (4 warps).
// weight role:  rw = t&63 (row), mhalf = (t>>6)*16 (m sub-range within 32-m chunk)
// accum role:   rp = t>>2 (rows 2rp,2rp+1), g4 = t&3 (cols g4*16..+15)
__global__ void __launch_bounds__(128, 6) k_attn() {
    __shared__ __align__(16) ulonglong2 hs2[2][32][16];  // 2 x (32 m x 64 cols)  16 KB
    __shared__ __align__(16) float4     mps[2][32];      // 2 x 32 m-params        1 KB
    __shared__ __align__(16) float      nums[32][64];    // weights [m][row]       8 KB

    const int t  = threadIdx.x;
    const int hd = blockIdx.y;
    const int n0 = blockIdx.x * 64;

    // ---- weight-role constants ----
    const int rw = t & 63;
    const int mhalf = (t >> 6) << 4;              // 0 or 16
    const int ridx = hd * NN + n0 + rw;
    const float sW  = g_src[ridx];
    const float e1W = g_E1[ridx];
    const float e2W = g_E2[ridx];
    const unsigned* __restrict__ adjrow = g_adj + (size_t)(n0 + rw) * 128;

    // ---- accumulation role ----
    const int rp = t >> 2, g4 = t & 3;

    u64 ac0[8], ac1[8];
#pragma unroll
    for (int q = 0; q < 8; q++) { ac0[q] = 0ull; ac1[q] = 0ull; }
    u64 Zp = 0ull;

    const ulonglong2* __restrict__ h4g =
        reinterpret_cast<const ulonglong2*>(g_h) + (size_t)hd * NN * 16;
    const float4* __restrict__ mpg = g_mp + hd * NN;

    // ---- prologue: stage chunk 0 ----
    {
#pragma unroll
        for (int j = 0; j < 4; j++) {
            int i = t + 128 * j;
            cpa16(&hs2[0][i >> 4][i & 15], &h4g[(size_t)(i >> 4) * 16 + (i & 15)]);
        }
        if (t < 32) cpa16(&mps[0][t], &mpg[t]);
        cpcommit();
    }
    unsigned aw_next = adjrow[0];

    for (int c = 0; c < 128; c++) {
        const int buf = c & 1;
        cpwait0();
        __syncthreads();                     // staged data visible; nums free

        // issue next chunk's loads (overlap with this chunk's compute)
        if (c + 1 < 128) {
            const int m1 = (c + 1) * 32;
            const int nb = buf ^ 1;
#pragma unroll
            for (int j = 0; j < 4; j++) {
                int i = t + 128 * j;
                cpa16(&hs2[nb][i >> 4][i & 15],
                      &h4g[(size_t)(m1 + (i >> 4)) * 16 + (i & 15)]);
            }
            if (t < 32) cpa16(&mps[nb][t], &mpg[m1 + t]);
            cpcommit();
        }
        const unsigned aw = aw_next;
        if (c + 1 < 128) aw_next = adjrow[c + 1];

        // ---- weight phase: 16 (row,m) weights per thread ----
#pragma unroll
        for (int j = 0; j < 16; j++) {
            const int m = mhalf + j;
            float4 p = mps[buf][m];                      // broadcast LDS.128
            float v = (sW >= p.x) ? e1W * p.y : e2W * p.z;
            nums[m][rw] = ((aw >> m) & 1u) ? v : 0.f;
        }
        __syncthreads();

        // ---- accumulate P @ h with packed f32x2 FMAs ----
#pragma unroll 8
        for (int m = 0; m < 32; m++) {
            float2 w = reinterpret_cast<const float2*>(nums[m])[rp];
            Zp = f2add(Zp, pack2(w.x, w.y));
            u64 w0 = pk2(w.x), w1 = pk2(w.y);
#pragma unroll
            for (int q = 0; q < 4; q++) {
                ulonglong2 hv = hs2[buf][m][g4 * 4 + q];
                ac0[2 * q]     = f2fma(hv.x, w0, ac0[2 * q]);
                ac0[2 * q + 1] = f2fma(hv.y, w0, ac0[2 * q + 1]);
                ac1[2 * q]     = f2fma(hv.x, w1, ac1[2 * q]);
                ac1[2 * q + 1] = f2fma(hv.y, w1, ac1[2 * q + 1]);
            }
        }
    }

    // ---- epilogue: normalize and store ----
    float Z0, Z1; unpack2(Zp, Z0, Z1);
    const u64 iz0 = pk2(1.f / Z0), iz1 = pk2(1.f / Z1);
    ulonglong2* o0 = reinterpret_cast<ulonglong2*>(g_hp) +
                     ((size_t)hd * NN + n0 + 2 * rp) * 16 + g4 * 4;
    ulonglong2* o1 = o0 + 16;
#pragma unroll
    for (int q = 0; q < 4; q++) {
        o0[q] = make_ulonglong2(f2mul(ac0[2 * q], iz0), f2mul(ac0[2 * q + 1], iz0));
        o1[q] = make_ulonglong2(f2mul(ac1[2 * q], iz1), f2mul(ac1[2 * q + 1], iz1));
    }
}

// ---------------- K5: mean over heads + ELU ----------------
__global__ void __launch_bounds__(256) k_final(float* __restrict__ out) {
    const int i = blockIdx.x * 256 + threadIdx.x;
    float s = 0.f;
#pragma unroll
    for (int hd = 0; hd < H; hd++) s += g_hp[(size_t)hd * NN * OUTF + i];
    s *= (1.f / H);
    out[i] = (s > 0.f) ? s : (__expf(s) - 1.f);
}

// ---------------- launch ----------------
extern "C" void kernel_launch(void* const* d_in, const int* in_sizes, int n_in,
                              void* d_out, int out_size) {
    const float* x   = (const float*)d_in[0];
    const int*   adj = (const int*)  d_in[1];
    const float* W   = (const float*)d_in[2];
    const float* a   = (const float*)d_in[3];
    float* out = (float*)d_out;

    k_gemm  <<<128, 512>>>(x, W);
    k_attvec<<<H * NN / 8, 256>>>(a);
    k_pack  <<<2048, 256>>>(adj);
    k_attn  <<<dim3(64, 8), 128>>>();
    k_final <<<NN * OUTF / 256, 256>>>(out);
}

// round 9
// speedup vs baseline: 2.6669x; 2.1800x over previous
#include <cuda_runtime.h>
#include <cuda_bf16.h>

#define NN   4096
#define INF  256
#define OUTF 64
#define H    8
#define GW   88          // padded G row width (bf16 cols): 64 h + 1 Z + pad

// ---------------- device scratch ----------------
__device__ float  g_h [H*NN*OUTF];              // projected features (8 MB)
__device__ float  g_hp[H*NN*OUTF];              // per-head attention output
__device__ float  g_s[H*NN], g_d[H*NN], g_ratio[H*NN];
__device__ __nv_bfloat16 g_G[2][2][H*NN*GW];    // [branch][hi/lo] G = diag(F)*[h|1|0] (23 MB)
__device__ unsigned g_adj[NN*(NN/32)];          // packed adjacency bitmask (2 MB)

// ---------------- helpers ----------------
__device__ __forceinline__ void cpa16(void* dst, const void* src) {
    unsigned ds = (unsigned)__cvta_generic_to_shared(dst);
    asm volatile("cp.async.ca.shared.global [%0], [%1], 16;" :: "r"(ds), "l"(src));
}
__device__ __forceinline__ void cpcommit() { asm volatile("cp.async.commit_group;"); }
__device__ __forceinline__ void cpwait0()  { asm volatile("cp.async.wait_group 0;"); }

__device__ __forceinline__ void ldsm4t(unsigned* r, unsigned addr) {
    asm volatile("ldmatrix.sync.aligned.m8n8.x4.trans.shared.b16 {%0,%1,%2,%3}, [%4];"
        : "=r"(r[0]), "=r"(r[1]), "=r"(r[2]), "=r"(r[3]) : "r"(addr));
}
__device__ __forceinline__ void mma16816(float* c, unsigned a0, unsigned a1,
                                         unsigned a2, unsigned a3,
                                         unsigned b0, unsigned b1) {
    asm volatile("mma.sync.aligned.m16n8k16.row.col.f32.bf16.bf16.f32 "
        "{%0,%1,%2,%3}, {%4,%5,%6,%7}, {%8,%9}, {%0,%1,%2,%3};"
        : "+f"(c[0]), "+f"(c[1]), "+f"(c[2]), "+f"(c[3])
        : "r"(a0), "r"(a1), "r"(a2), "r"(a3), "r"(b0), "r"(b1));
}
__device__ __forceinline__ unsigned bpair(bool c0, bool c1) {
    return (c0 ? 0x00003F80u : 0u) | (c1 ? 0x3F800000u : 0u);   // {bf16(1), bf16(1)}
}
__device__ __forceinline__ void bf16split(float x, __nv_bfloat16& hi, __nv_bfloat16& lo) {
    hi = __float2bfloat16(x);
    lo = __float2bfloat16(x - __bfloat162float(hi));
}

// ---------------- K1: h = x @ W ----------------
__global__ void __launch_bounds__(512) k_gemm(const float* __restrict__ x,
                                              const float* __restrict__ W) {
    __shared__ float4 xs[32][64];
    const int t  = threadIdx.x;
    const int n0 = blockIdx.x * 32;
    const float4* x4 = reinterpret_cast<const float4*>(x) + (size_t)n0 * 64;
    for (int i = t; i < 32 * 64; i += 512) xs[i >> 6][i & 63] = x4[(i >> 6) * 64 + (i & 63)];
    __syncthreads();

    const int hd = t >> 6, o = t & 63;
    const float* Wp = W + hd * INF * OUTF + o;
    float acc[32];
#pragma unroll
    for (int r = 0; r < 32; r++) acc[r] = 0.f;
    for (int k4 = 0; k4 < 64; k4++) {
        float w0 = Wp[(4 * k4 + 0) * OUTF];
        float w1 = Wp[(4 * k4 + 1) * OUTF];
        float w2 = Wp[(4 * k4 + 2) * OUTF];
        float w3 = Wp[(4 * k4 + 3) * OUTF];
#pragma unroll
        for (int r = 0; r < 32; r++) {
            float4 xv = xs[r][k4];
            acc[r] += xv.x * w0 + xv.y * w1 + xv.z * w2 + xv.w * w3;
        }
    }
#pragma unroll
    for (int r = 0; r < 32; r++)
        g_h[((size_t)hd * NN + n0 + r) * OUTF + o] = acc[r];
}

// ---------------- K2: attention vectors + G matrices (bf16 hi/lo) ----------------
__global__ void __launch_bounds__(256) k_attvec(const float* __restrict__ a) {
    const int warp = (blockIdx.x * blockDim.x + threadIdx.x) >> 5;
    const int lane = threadIdx.x & 31;
    if (warp >= H * NN) return;
    const int hd = warp >> 12;
    const float* hv = g_h + (size_t)warp * OUTF;
    const float* ap = a + hd * (2 * OUTF);
    float v0 = hv[lane], v1 = hv[32 + lane];
    float s = v0 * ap[lane]      + v1 * ap[32 + lane];
    float d = v0 * ap[64 + lane] + v1 * ap[96 + lane];
#pragma unroll
    for (int off = 16; off; off >>= 1) {
        s += __shfl_xor_sync(~0u, s, off);
        d += __shfl_xor_sync(~0u, d, off);
    }
    const float F1 = __expf(d), F2 = __expf(0.2f * d);
    const size_t gb = (size_t)warp * GW;
    __nv_bfloat16 hi, lo;
    // branch 0: F1 * h ; branch 1: F2 * h  (cols lane, lane+32)
    bf16split(F1 * v0, hi, lo); g_G[0][0][gb + lane] = hi;      g_G[0][1][gb + lane] = lo;
    bf16split(F1 * v1, hi, lo); g_G[0][0][gb + 32 + lane] = hi; g_G[0][1][gb + 32 + lane] = lo;
    bf16split(F2 * v0, hi, lo); g_G[1][0][gb + lane] = hi;      g_G[1][1][gb + lane] = lo;
    bf16split(F2 * v1, hi, lo); g_G[1][0][gb + 32 + lane] = hi; g_G[1][1][gb + 32 + lane] = lo;
    if (lane == 0) {            // Z column (64) = F itself
        bf16split(F1, hi, lo); g_G[0][0][gb + 64] = hi; g_G[0][1][gb + 64] = lo;
        bf16split(F2, hi, lo); g_G[1][0][gb + 64] = hi; g_G[1][1][gb + 64] = lo;
        g_s[warp] = s; g_d[warp] = d; g_ratio[warp] = __expf(0.8f * s);
    } else if (lane < 24) {     // zero-pad cols 65..87
        __nv_bfloat16 z = __float2bfloat16(0.f);
        g_G[0][0][gb + 64 + lane] = z; g_G[0][1][gb + 64 + lane] = z;
        g_G[1][0][gb + 64 + lane] = z; g_G[1][1][gb + 64 + lane] = z;
    }
}

// ---------------- K3: pack adjacency ----------------
__global__ void __launch_bounds__(256) k_pack(const int* __restrict__ adj) {
    const int warp = (blockIdx.x * blockDim.x + threadIdx.x) >> 5;
    const int lane = threadIdx.x & 31;
    const int base = warp * 32;
#pragma unroll 4
    for (int i = 0; i < 32; i++) {
        unsigned m = __ballot_sync(~0u, adj[(size_t)(base + i) * 32 + lane] != 0);
        if (lane == 0) g_adj[base + i] = m;
    }
}

// ---------------- K4: binary-matrix tensor-core attention ----------------
// grid (32, 8): 128-row tile x head.  256 threads = 8 warps.
// warp wid: row-group rg = wid>>1 (32 rows), n-half nh = wid&1 (40 cols of 80).
// Two k-passes (branch 0, branch 1) into one accumulator, scaled by exp(0.8s) between.
__global__ void __launch_bounds__(256, 2) k_attn_mma() {
    __shared__ __align__(16) __nv_bfloat16 Gs[2][2][16][GW];   // [buf][hi/lo][k][col]
    __shared__ float zbuf[128];

    const int t    = threadIdx.x;
    const int lane = t & 31, wid = t >> 5;
    const int hd   = blockIdx.y;
    const int n0   = blockIdx.x * 128;
    const int rg   = wid >> 1, nh = wid & 1;
    const int R0   = rg * 32;
    const int NB   = nh * 40;
    const int g    = lane >> 2, tig = lane & 3;
    const int kc   = tig * 2;

    int rows[4] = { R0 + g, R0 + 8 + g, R0 + 16 + g, R0 + 24 + g };  // block-local
    const int ridx0 = hd * NN + n0;
    float s[4];
    const unsigned* adjp[4];
#pragma unroll
    for (int i = 0; i < 4; i++) {
        s[i] = g_s[ridx0 + rows[i]];
        adjp[i] = g_adj + (size_t)(n0 + rows[i]) * 128;
    }
    const float* __restrict__ dptr = g_d + hd * NN;

    float acc[2][5][4];
#pragma unroll
    for (int tt = 0; tt < 2; tt++)
#pragma unroll
        for (int nt = 0; nt < 5; nt++)
#pragma unroll
            for (int q = 0; q < 4; q++) acc[tt][nt][q] = 0.f;

#pragma unroll
    for (int br = 0; br < 2; br++) {
        const __nv_bfloat16* __restrict__ Ghi = g_G[br][0] + (size_t)hd * NN * GW;
        const __nv_bfloat16* __restrict__ Glo = g_G[br][1] + (size_t)hd * NN * GW;

        // prologue: stage chunk 0 into buf 0
        for (int i = t; i < 352; i += 256) {
            int arr = i / 176, rem = i - arr * 176;
            int row = rem / 11, c16 = rem - row * 11;
            cpa16(&Gs[0][arr][row][c16 * 8],
                  (arr ? Glo : Ghi) + (size_t)row * GW + c16 * 8);
        }
        cpcommit();
        unsigned wcur[4], wnxt[4];
#pragma unroll
        for (int i = 0; i < 4; i++) wcur[i] = adjp[i][0];

        for (int c = 0; c < 256; c++) {
            const int buf = c & 1;
            cpwait0();
            __syncthreads();
            if (c + 1 < 256) {
                const int nb = buf ^ 1;
                const size_t mo = (size_t)(c + 1) * 16;
                for (int i = t; i < 352; i += 256) {
                    int arr = i / 176, rem = i - arr * 176;
                    int row = rem / 11, c16 = rem - row * 11;
                    cpa16(&Gs[nb][arr][row][c16 * 8],
                          (arr ? Glo : Ghi) + (mo + row) * GW + c16 * 8);
                }
                cpcommit();
            }
            // adjacency word prefetch (one word = 2 chunks)
            if (!(c & 1)) {
                int wi = (c >> 1) + 1;
                if (wi < 128) {
#pragma unroll
                    for (int i = 0; i < 4; i++) wnxt[i] = adjp[i][wi];
                }
            }
            const int bitb = (c & 1) * 16;
            const float2 dlo = *(const float2*)(dptr + c * 16 + kc);
            const float2 dhi = *(const float2*)(dptr + c * 16 + kc + 8);

            // ---- build binary A fragments in registers ----
            unsigned A[2][4];
#pragma unroll
            for (int tt = 0; tt < 2; tt++) {
                const int ra = 2 * tt, rb = 2 * tt + 1;
                const unsigned wa = wcur[ra] >> bitb, wb = wcur[rb] >> bitb;
                bool pa0 = ((s[ra] + dlo.x >= 0.f) != (br == 1));
                bool pa1 = ((s[ra] + dlo.y >= 0.f) != (br == 1));
                bool pa2 = ((s[ra] + dhi.x >= 0.f) != (br == 1));
                bool pa3 = ((s[ra] + dhi.y >= 0.f) != (br == 1));
                bool pb0 = ((s[rb] + dlo.x >= 0.f) != (br == 1));
                bool pb1 = ((s[rb] + dlo.y >= 0.f) != (br == 1));
                bool pb2 = ((s[rb] + dhi.x >= 0.f) != (br == 1));
                bool pb3 = ((s[rb] + dhi.y >= 0.f) != (br == 1));
                A[tt][0] = bpair(((wa >> kc) & 1) && pa0, ((wa >> (kc + 1)) & 1) && pa1);
                A[tt][1] = bpair(((wb >> kc) & 1) && pb0, ((wb >> (kc + 1)) & 1) && pb1);
                A[tt][2] = bpair(((wa >> (kc + 8)) & 1) && pa2, ((wa >> (kc + 9)) & 1) && pa3);
                A[tt][3] = bpair(((wb >> (kc + 8)) & 1) && pb2, ((wb >> (kc + 9)) & 1) && pb3);
            }
            if (c & 1) {
#pragma unroll
                for (int i = 0; i < 4; i++) wcur[i] = wnxt[i];
            }

            // ---- hi/lo split GEMMs ----
#pragma unroll
            for (int sp = 0; sp < 2; sp++) {
                unsigned sb = (unsigned)__cvta_generic_to_shared(&Gs[buf][sp][0][0]);
                unsigned la = sb + (lane & 15) * (GW * 2) + ((lane & 16) ? 16 : 0);
                unsigned b[3][4];
#pragma unroll
                for (int q = 0; q < 3; q++)
                    ldsm4t(b[q], la + (NB + q * 16) * 2);
#pragma unroll
                for (int tt = 0; tt < 2; tt++)
#pragma unroll
                    for (int nt = 0; nt < 5; nt++) {
                        const unsigned* bb = b[nt >> 1] + (nt & 1) * 2;
                        mma16816(acc[tt][nt], A[tt][0], A[tt][1], A[tt][2], A[tt][3],
                                 bb[0], bb[1]);
                    }
            }
        }

        // between passes: scale branch-0 partials by exp(0.8 s_row)
        if (br == 0) {
            float rat[4];
#pragma unroll
            for (int i = 0; i < 4; i++) rat[i] = g_ratio[ridx0 + rows[i]];
#pragma unroll
            for (int tt = 0; tt < 2; tt++)
#pragma unroll
                for (int nt = 0; nt < 5; nt++) {
                    acc[tt][nt][0] *= rat[2 * tt];     acc[tt][nt][1] *= rat[2 * tt];
                    acc[tt][nt][2] *= rat[2 * tt + 1]; acc[tt][nt][3] *= rat[2 * tt + 1];
                }
        }
    }

    // ---- epilogue: Z broadcast + normalize + store ----
    if (nh == 1 && tig == 0) {       // col 64 lives in n-half 1, n-tile 3, tig 0
#pragma unroll
        for (int tt = 0; tt < 2; tt++) {
            zbuf[rows[2 * tt]]     = acc[tt][3][0];
            zbuf[rows[2 * tt + 1]] = acc[tt][3][2];
        }
    }
    __syncthreads();
    float rz[4];
#pragma unroll
    for (int i = 0; i < 4; i++) rz[i] = 1.f / zbuf[rows[i]];

    float* __restrict__ hp = g_hp + ((size_t)hd * NN + n0) * OUTF;
#pragma unroll
    for (int tt = 0; tt < 2; tt++)
#pragma unroll
        for (int nt = 0; nt < 5; nt++) {
            const int col0 = NB + nt * 8;
            if (col0 < 64) {
                const int col = col0 + kc;
                float2 o0 = make_float2(acc[tt][nt][0] * rz[2 * tt],
                                        acc[tt][nt][1] * rz[2 * tt]);
                float2 o1 = make_float2(acc[tt][nt][2] * rz[2 * tt + 1],
                                        acc[tt][nt][3] * rz[2 * tt + 1]);
                *(float2*)(hp + (size_t)rows[2 * tt] * OUTF + col)     = o0;
                *(float2*)(hp + (size_t)rows[2 * tt + 1] * OUTF + col) = o1;
            }
        }
}

// ---------------- K5: mean over heads + ELU ----------------
__global__ void __launch_bounds__(256) k_final(float* __restrict__ out) {
    const int i = blockIdx.x * 256 + threadIdx.x;
    float s = 0.f;
#pragma unroll
    for (int hd = 0; hd < H; hd++) s += g_hp[(size_t)hd * NN * OUTF + i];
    s *= (1.f / H);
    out[i] = (s > 0.f) ? s : (__expf(s) - 1.f);
}

// ---------------- launch ----------------
extern "C" void kernel_launch(void* const* d_in, const int* in_sizes, int n_in,
                              void* d_out, int out_size) {
    const float* x   = (const float*)d_in[0];
    const int*   adj = (const int*)  d_in[1];
    const float* W   = (const float*)d_in[2];
    const float* a   = (const float*)d_in[3];
    float* out = (float*)d_out;

    k_gemm    <<<128, 512>>>(x, W);
    k_attvec  <<<H * NN / 8, 256>>>(a);
    k_pack    <<<2048, 256>>>(adj);
    k_attn_mma<<<dim3(32, 8), 256>>>();
    k_final   <<<NN * OUTF / 256, 256>>>(out);
}

// round 13
// speedup vs baseline: 2.7767x; 1.0412x over previous
#include <cuda_runtime.h>
#include <cuda_bf16.h>

#define NN   4096
#define INF  256
#define OUTF 64
#define H    8
#define GW   72          // G row width (bf16): 64 h + 1 Z + 7 pad (144B stride, conflict-free)

// ---------------- device scratch ----------------
__device__ float  g_h [H*NN*OUTF];              // projected features (8 MB)
__device__ float  g_hp[H*NN*OUTF];              // per-head attention output
__device__ float  g_s[H*NN], g_d[H*NN], g_ratio[H*NN];
__device__ __nv_bfloat16 g_G[2][2][H*NN*GW];    // [branch][hi/lo] G = diag(F)*[h|1|0] (19 MB)
__device__ unsigned g_adj[NN*(NN/32)];          // packed adjacency (2 MB, head-indep)
__device__ unsigned g_P[H*NN*(NN/32)];          // predicate bitmask s_r+d_m>=0 (16 MB)

// ---------------- helpers ----------------
__device__ __forceinline__ void cpa16(void* dst, const void* src) {
    unsigned ds = (unsigned)__cvta_generic_to_shared(dst);
    asm volatile("cp.async.ca.shared.global [%0], [%1], 16;" :: "r"(ds), "l"(src));
}
__device__ __forceinline__ void cpcommit() { asm volatile("cp.async.commit_group;"); }
__device__ __forceinline__ void cpwait0()  { asm volatile("cp.async.wait_group 0;"); }

__device__ __forceinline__ void ldsm4t(unsigned* r, unsigned addr) {
    asm volatile("ldmatrix.sync.aligned.m8n8.x4.trans.shared.b16 {%0,%1,%2,%3}, [%4];"
        : "=r"(r[0]), "=r"(r[1]), "=r"(r[2]), "=r"(r[3]) : "r"(addr));
}
__device__ __forceinline__ void mma16816(float* c, unsigned a0, unsigned a1,
                                         unsigned a2, unsigned a3,
                                         unsigned b0, unsigned b1) {
    asm volatile("mma.sync.aligned.m16n8k16.row.col.f32.bf16.bf16.f32 "
        "{%0,%1,%2,%3}, {%4,%5,%6,%7}, {%8,%9}, {%0,%1,%2,%3};"
        : "+f"(c[0]), "+f"(c[1]), "+f"(c[2]), "+f"(c[3])
        : "r"(a0), "r"(a1), "r"(a2), "r"(a3), "r"(b0), "r"(b1));
}
// two mask bits (k, k+1) -> packed {bf16(1|0), bf16(1|0)}
__device__ __forceinline__ unsigned bp2(unsigned w, int k) {
    return ((w >> k) & 1u) * 0x3F80u + ((w >> (k + 1)) & 1u) * 0x3F800000u;
}
__device__ __forceinline__ void bf16split(float x, __nv_bfloat16& hi, __nv_bfloat16& lo) {
    hi = __float2bfloat16(x);
    lo = __float2bfloat16(x - __bfloat162float(hi));
}

// ---------------- K1: h = x @ W ----------------
__global__ void __launch_bounds__(512) k_gemm(const float* __restrict__ x,
                                              const float* __restrict__ W) {
    __shared__ float4 xs[32][64];
    const int t  = threadIdx.x;
    const int n0 = blockIdx.x * 32;
    const float4* x4 = reinterpret_cast<const float4*>(x) + (size_t)n0 * 64;
    for (int i = t; i < 32 * 64; i += 512) xs[i >> 6][i & 63] = x4[(i >> 6) * 64 + (i & 63)];
    __syncthreads();

    const int hd = t >> 6, o = t & 63;
    const float* Wp = W + hd * INF * OUTF + o;
    float acc[32];
#pragma unroll
    for (int r = 0; r < 32; r++) acc[r] = 0.f;
    for (int k4 = 0; k4 < 64; k4++) {
        float w0 = Wp[(4 * k4 + 0) * OUTF];
        float w1 = Wp[(4 * k4 + 1) * OUTF];
        float w2 = Wp[(4 * k4 + 2) * OUTF];
        float w3 = Wp[(4 * k4 + 3) * OUTF];
#pragma unroll
        for (int r = 0; r < 32; r++) {
            float4 xv = xs[r][k4];
            acc[r] += xv.x * w0 + xv.y * w1 + xv.z * w2 + xv.w * w3;
        }
    }
#pragma unroll
    for (int r = 0; r < 32; r++)
        g_h[((size_t)hd * NN + n0 + r) * OUTF + o] = acc[r];
}

// ---------------- K2: attention vectors + G matrices (bf16 hi/lo) ----------------
__global__ void __launch_bounds__(256) k_attvec(const float* __restrict__ a) {
    const int warp = (blockIdx.x * blockDim.x + threadIdx.x) >> 5;
    const int lane = threadIdx.x & 31;
    if (warp >= H * NN) return;
    const int hd = warp >> 12;
    const float* hv = g_h + (size_t)warp * OUTF;
    const float* ap = a + hd * (2 * OUTF);
    float v0 = hv[lane], v1 = hv[32 + lane];
    float s = v0 * ap[lane]      + v1 * ap[32 + lane];
    float d = v0 * ap[64 + lane] + v1 * ap[96 + lane];
#pragma unroll
    for (int off = 16; off; off >>= 1) {
        s += __shfl_xor_sync(~0u, s, off);
        d += __shfl_xor_sync(~0u, d, off);
    }
    const float F1 = __expf(d), F2 = __expf(0.2f * d);
    const size_t gb = (size_t)warp * GW;
    __nv_bfloat16 hi, lo;
    bf16split(F1 * v0, hi, lo); g_G[0][0][gb + lane] = hi;      g_G[0][1][gb + lane] = lo;
    bf16split(F1 * v1, hi, lo); g_G[0][0][gb + 32 + lane] = hi; g_G[0][1][gb + 32 + lane] = lo;
    bf16split(F2 * v0, hi, lo); g_G[1][0][gb + lane] = hi;      g_G[1][1][gb + lane] = lo;
    bf16split(F2 * v1, hi, lo); g_G[1][0][gb + 32 + lane] = hi; g_G[1][1][gb + 32 + lane] = lo;
    if (lane == 0) {            // Z column (64) = F itself
        bf16split(F1, hi, lo); g_G[0][0][gb + 64] = hi; g_G[0][1][gb + 64] = lo;
        bf16split(F2, hi, lo); g_G[1][0][gb + 64] = hi; g_G[1][1][gb + 64] = lo;
        g_s[warp] = s; g_d[warp] = d; g_ratio[warp] = __expf(0.8f * s);
    } else if (lane < 8) {      // zero-pad cols 65..71
        __nv_bfloat16 z = __float2bfloat16(0.f);
        g_G[0][0][gb + 64 + lane] = z; g_G[0][1][gb + 64 + lane] = z;
        g_G[1][0][gb + 64 + lane] = z; g_G[1][1][gb + 64 + lane] = z;
    }
}

// ---------------- K3: pack adjacency ----------------
__global__ void __launch_bounds__(256) k_pack(const int* __restrict__ adj) {
    const int warp = (blockIdx.x * blockDim.x + threadIdx.x) >> 5;
    const int lane = threadIdx.x & 31;
    const int base = warp * 32;
#pragma unroll 4
    for (int i = 0; i < 32; i++) {
        unsigned m = __ballot_sync(~0u, adj[(size_t)(base + i) * 32 + lane] != 0);
        if (lane == 0) g_adj[base + i] = m;
    }
}

// ---------------- K3b: predicate bitmask P[h][r][m] = (s_r + d_m >= 0) ----------------
// grid (NN/8, H), 256 threads: warp per row, d[head] cached in smem.
__global__ void __launch_bounds__(256) k_pred() {
    __shared__ float ds[NN];
    const int hd = blockIdx.y;
    const int t  = threadIdx.x;
    const float4* d4 = reinterpret_cast<const float4*>(g_d + hd * NN);
    float4* ds4 = reinterpret_cast<float4*>(ds);
    for (int i = t; i < NN / 4; i += 256) ds4[i] = d4[i];
    __syncthreads();
    const int wr = t >> 5, lane = t & 31;
    const int R  = blockIdx.x * 8 + wr;
    const float s = g_s[hd * NN + R];
    unsigned* Pr = g_P + ((size_t)hd * NN + R) * 128;
#pragma unroll 4
    for (int wi = 0; wi < 128; wi++) {
        unsigned b = __ballot_sync(~0u, s + ds[wi * 32 + lane] >= 0.f);
        if (lane == 0) Pr[wi] = b;
    }
}

// ---------------- K4: binary-matrix tensor-core attention ----------------
// grid (32, 8): 128-row tile x head. 8 warps: rg = wid>>1 (32 rows), nh = wid&1.
// nh=0 -> cols 0..39 (5 n-tiles); nh=1 -> cols 40..71 (4 n-tiles, incl. Z col 64).
// 32-k chunks == one adjacency/predicate word. Two passes (branch), ratio-scaled.
__global__ void __launch_bounds__(256, 3) k_attn_mma() {
    __shared__ __align__(16) __nv_bfloat16 Gs[2][2][32][GW];   // [buf][sp][k][col] 18 KB
    __shared__ float zbuf[128];

    const int t    = threadIdx.x;
    const int lane = t & 31, wid = t >> 5;
    const int hd   = blockIdx.y;
    const int n0   = blockIdx.x * 128;
    const int rg   = wid >> 1, nh = wid & 1;
    const int R0   = rg * 32;
    const int NB   = nh * 40;
    const int NT   = nh ? 4 : 5;
    const int NQ   = nh ? 2 : 3;
    const int g    = lane >> 2, tig = lane & 3;
    const int kc   = tig * 2;

    int rows[4] = { R0 + g, R0 + 8 + g, R0 + 16 + g, R0 + 24 + g };
    const int ridx0 = hd * NN + n0;
    const unsigned* __restrict__ adjp = g_adj + (size_t)n0 * 128;
    const unsigned* __restrict__ Pp   = g_P + (size_t)ridx0 * 128;

    float acc[2][5][4];
#pragma unroll
    for (int tt = 0; tt < 2; tt++)
#pragma unroll
        for (int nt = 0; nt < 5; nt++)
#pragma unroll
            for (int q = 0; q < 4; q++) acc[tt][nt][q] = 0.f;

#pragma unroll
    for (int br = 0; br < 2; br++) {
        const __nv_bfloat16* __restrict__ Ghi = g_G[br][0] + (size_t)hd * NN * GW;
        const __nv_bfloat16* __restrict__ Glo = g_G[br][1] + (size_t)hd * NN * GW;

        // prologue: stage chunk 0 into buf 0 (2 sp x 32 rows x 9 x 16B = 576)
        for (int i = t; i < 576; i += 256) {
            int sp = i / 288, rem = i - sp * 288;
            int row = rem / 9, c16 = rem - row * 9;
            cpa16(&Gs[0][sp][row][c16 * 8],
                  (sp ? Glo : Ghi) + (size_t)row * GW + c16 * 8);
        }
        cpcommit();
        unsigned wcur[4];
#pragma unroll
        for (int i = 0; i < 4; i++) {
            unsigned aw = adjp[rows[i] * 128], pw = Pp[rows[i] * 128];
            wcur[i] = br ? (aw & ~pw) : (aw & pw);
        }

        for (int c = 0; c < 128; c++) {
            const int buf = c & 1;
            cpwait0();
            __syncthreads();
            if (c + 1 < 128) {
                const int nb = buf ^ 1;
                const size_t mo = (size_t)(c + 1) * 32;
                for (int i = t; i < 576; i += 256) {
                    int sp = i / 288, rem = i - sp * 288;
                    int row = rem / 9, c16 = rem - row * 9;
                    cpa16(&Gs[nb][sp][row][c16 * 8],
                          (sp ? Glo : Ghi) + (mo + row) * GW + c16 * 8);
                }
                cpcommit();
            }
            unsigned wnxt[4];
            if (c + 1 < 128) {
#pragma unroll
                for (int i = 0; i < 4; i++) {
                    unsigned aw = adjp[rows[i] * 128 + c + 1];
                    unsigned pw = Pp[rows[i] * 128 + c + 1];
                    wnxt[i] = br ? (aw & ~pw) : (aw & pw);
                }
            }

#pragma unroll
            for (int kt = 0; kt < 2; kt++) {
                // A fragments: pure bit->bf16 packing from precombined mask
                unsigned A[2][4];
#pragma unroll
                for (int tt = 0; tt < 2; tt++) {
                    const unsigned wa = wcur[2 * tt]     >> (kt * 16);
                    const unsigned wb = wcur[2 * tt + 1] >> (kt * 16);
                    A[tt][0] = bp2(wa, kc);
                    A[tt][1] = bp2(wb, kc);
                    A[tt][2] = bp2(wa, kc + 8);
                    A[tt][3] = bp2(wb, kc + 8);
                }
#pragma unroll
                for (int sp = 0; sp < 2; sp++) {
                    unsigned sb = (unsigned)__cvta_generic_to_shared(&Gs[buf][sp][0][0]);
                    unsigned la = sb + (kt * 16 + (lane & 15)) * (GW * 2)
                                     + ((lane & 16) ? 16 : 0);
                    unsigned b[3][4];
#pragma unroll
                    for (int q = 0; q < 3; q++)
                        if (q < NQ + (nh ? 0 : 0) && q < (nh ? 2 : 3))
                            ldsm4t(b[q], la + (NB + q * 16) * 2);
#pragma unroll
                    for (int tt = 0; tt < 2; tt++)
#pragma unroll
                        for (int nt = 0; nt < 5; nt++)
                            if (nt < NT) {
                                const unsigned* bb = b[nt >> 1] + (nt & 1) * 2;
                                mma16816(acc[tt][nt], A[tt][0], A[tt][1],
                                         A[tt][2], A[tt][3], bb[0], bb[1]);
                            }
                }
            }
#pragma unroll
            for (int i = 0; i < 4; i++) wcur[i] = wnxt[i];
        }

        // between passes: scale branch-0 partials by exp(0.8 s_row)
        if (br == 0) {
            float rat[4];
#pragma unroll
            for (int i = 0; i < 4; i++) rat[i] = g_ratio[ridx0 + rows[i]];
#pragma unroll
            for (int tt = 0; tt < 2; tt++)
#pragma unroll
                for (int nt = 0; nt < 5; nt++) {
                    acc[tt][nt][0] *= rat[2 * tt];     acc[tt][nt][1] *= rat[2 * tt];
                    acc[tt][nt][2] *= rat[2 * tt + 1]; acc[tt][nt][3] *= rat[2 * tt + 1];
                }
        }
    }

    // ---- epilogue: Z broadcast + normalize + store ----
    if (nh == 1 && tig == 0) {       // col 64 = Z lives at nh=1, nt=3, tig=0
#pragma unroll
        for (int tt = 0; tt < 2; tt++) {
            zbuf[rows[2 * tt]]     = acc[tt][3][0];
            zbuf[rows[2 * tt + 1]] = acc[tt][3][2];
        }
    }
    __syncthreads();
    float rz[4];
#pragma unroll
    for (int i = 0; i < 4; i++) rz[i] = 1.f / zbuf[rows[i]];

    float* __restrict__ hp = g_hp + ((size_t)hd * NN + n0) * OUTF;
#pragma unroll
    for (int tt = 0; tt < 2; tt++)
#pragma unroll
        for (int nt = 0; nt < 5; nt++) {
            const int col0 = NB + nt * 8;
            if (nt < NT && col0 < 64) {
                const int col = col0 + kc;
                float2 o0 = make_float2(acc[tt][nt][0] * rz[2 * tt],
                                        acc[tt][nt][1] * rz[2 * tt]);
                float2 o1 = make_float2(acc[tt][nt][2] * rz[2 * tt + 1],
                                        acc[tt][nt][3] * rz[2 * tt + 1]);
                *(float2*)(hp + (size_t)rows[2 * tt] * OUTF + col)     = o0;
                *(float2*)(hp + (size_t)rows[2 * tt + 1] * OUTF + col) = o1;
            }
        }
}

// ---------------- K5: mean over heads + ELU ----------------
__global__ void __launch_bounds__(256) k_final(float* __restrict__ out) {
    const int i = blockIdx.x * 256 + threadIdx.x;
    float s = 0.f;
#pragma unroll
    for (int hd = 0; hd < H; hd++) s += g_hp[(size_t)hd * NN * OUTF + i];
    s *= (1.f / H);
    out[i] = (s > 0.f) ? s : (__expf(s) - 1.f);
}

// ---------------- launch ----------------
extern "C" void kernel_launch(void* const* d_in, const int* in_sizes, int n_in,
                              void* d_out, int out_size) {
    const float* x   = (const float*)d_in[0];
    const int*   adj = (const int*)  d_in[1];
    const float* W   = (const float*)d_in[2];
    const float* a   = (const float*)d_in[3];
    float* out = (float*)d_out;

    k_gemm    <<<128, 512>>>(x, W);
    k_attvec  <<<H * NN / 8, 256>>>(a);
    k_pack    <<<2048, 256>>>(adj);
    k_pred    <<<dim3(NN / 8, H), 256>>>();
    k_attn_mma<<<dim3(32, 8), 256>>>();
    k_final   <<<NN * OUTF / 256, 256>>>(out);
}

// round 14
// speedup vs baseline: 3.0162x; 1.0863x over previous
#include <cuda_runtime.h>
#include <cuda_bf16.h>

#define NN   4096
#define INF  256
#define OUTF 64
#define H    8
#define GW   72          // G row width (bf16): 64 h + 1 Z + 7 pad (144B stride, conflict-free)

// ---------------- device scratch ----------------
__device__ float  g_h [H*NN*OUTF];              // projected features (8 MB)
__device__ float  g_hp[H*NN*OUTF];              // per-head attention output
__device__ float  g_s[H*NN], g_d[H*NN], g_ratio[H*NN];
__device__ __nv_bfloat16 g_G[2][2][H*NN*GW];    // [branch][hi/lo] G = diag(F)*[h|1|0] (19 MB)
__device__ unsigned g_adj[NN*(NN/32)];          // packed adjacency (2 MB, head-indep)
__device__ unsigned g_P[H*NN*(NN/32)];          // predicate bitmask s_r+d_m>=0 (16 MB)

// ---------------- helpers ----------------
__device__ __forceinline__ void cpa16(void* dst, const void* src) {
    unsigned ds = (unsigned)__cvta_generic_to_shared(dst);
    asm volatile("cp.async.ca.shared.global [%0], [%1], 16;" :: "r"(ds), "l"(src));
}
__device__ __forceinline__ void cpcommit() { asm volatile("cp.async.commit_group;"); }
template <int N>
__device__ __forceinline__ void cpwait() {
    asm volatile("cp.async.wait_group %0;" :: "n"(N));
}

__device__ __forceinline__ void ldsm4t(unsigned* r, unsigned addr) {
    asm volatile("ldmatrix.sync.aligned.m8n8.x4.trans.shared.b16 {%0,%1,%2,%3}, [%4];"
        : "=r"(r[0]), "=r"(r[1]), "=r"(r[2]), "=r"(r[3]) : "r"(addr));
}
__device__ __forceinline__ void mma16816(float* c, unsigned a0, unsigned a1,
                                         unsigned a2, unsigned a3,
                                         unsigned b0, unsigned b1) {
    asm volatile("mma.sync.aligned.m16n8k16.row.col.f32.bf16.bf16.f32 "
        "{%0,%1,%2,%3}, {%4,%5,%6,%7}, {%8,%9}, {%0,%1,%2,%3};"
        : "+f"(c[0]), "+f"(c[1]), "+f"(c[2]), "+f"(c[3])
        : "r"(a0), "r"(a1), "r"(a2), "r"(a3), "r"(b0), "r"(b1));
}
// two mask bits (k, k+1) -> packed {bf16(1|0), bf16(1|0)}
__device__ __forceinline__ unsigned bp2(unsigned w, int k) {
    return ((w >> k) & 1u) * 0x3F80u + ((w >> (k + 1)) & 1u) * 0x3F800000u;
}
__device__ __forceinline__ void bf16split(float x, __nv_bfloat16& hi, __nv_bfloat16& lo) {
    hi = __float2bfloat16(x);
    lo = __float2bfloat16(x - __bfloat162float(hi));
}

// ---------------- K1: h = x @ W ----------------
__global__ void __launch_bounds__(512) k_gemm(const float* __restrict__ x,
                                              const float* __restrict__ W) {
    __shared__ float4 xs[32][64];
    const int t  = threadIdx.x;
    const int n0 = blockIdx.x * 32;
    const float4* x4 = reinterpret_cast<const float4*>(x) + (size_t)n0 * 64;
    for (int i = t; i < 32 * 64; i += 512) xs[i >> 6][i & 63] = x4[(i >> 6) * 64 + (i & 63)];
    __syncthreads();

    const int hd = t >> 6, o = t & 63;
    const float* Wp = W + hd * INF * OUTF + o;
    float acc[32];
#pragma unroll
    for (int r = 0; r < 32; r++) acc[r] = 0.f;
    for (int k4 = 0; k4 < 64; k4++) {
        float w0 = Wp[(4 * k4 + 0) * OUTF];
        float w1 = Wp[(4 * k4 + 1) * OUTF];
        float w2 = Wp[(4 * k4 + 2) * OUTF];
        float w3 = Wp[(4 * k4 + 3) * OUTF];
#pragma unroll
        for (int r = 0; r < 32; r++) {
            float4 xv = xs[r][k4];
            acc[r] += xv.x * w0 + xv.y * w1 + xv.z * w2 + xv.w * w3;
        }
    }
#pragma unroll
    for (int r = 0; r < 32; r++)
        g_h[((size_t)hd * NN + n0 + r) * OUTF + o] = acc[r];
}

// ---------------- K2: attention vectors + G matrices (bf16 hi/lo) ----------------
__global__ void __launch_bounds__(256) k_attvec(const float* __restrict__ a) {
    const int warp = (blockIdx.x * blockDim.x + threadIdx.x) >> 5;
    const int lane = threadIdx.x & 31;
    if (warp >= H * NN) return;
    const int hd = warp >> 12;
    const float* hv = g_h + (size_t)warp * OUTF;
    const float* ap = a + hd * (2 * OUTF);
    float v0 = hv[lane], v1 = hv[32 + lane];
    float s = v0 * ap[lane]      + v1 * ap[32 + lane];
    float d = v0 * ap[64 + lane] + v1 * ap[96 + lane];
#pragma unroll
    for (int off = 16; off; off >>= 1) {
        s += __shfl_xor_sync(~0u, s, off);
        d += __shfl_xor_sync(~0u, d, off);
    }
    const float F1 = __expf(d), F2 = __expf(0.2f * d);
    const size_t gb = (size_t)warp * GW;
    __nv_bfloat16 hi, lo;
    bf16split(F1 * v0, hi, lo); g_G[0][0][gb + lane] = hi;      g_G[0][1][gb + lane] = lo;
    bf16split(F1 * v1, hi, lo); g_G[0][0][gb + 32 + lane] = hi; g_G[0][1][gb + 32 + lane] = lo;
    bf16split(F2 * v0, hi, lo); g_G[1][0][gb + lane] = hi;      g_G[1][1][gb + lane] = lo;
    bf16split(F2 * v1, hi, lo); g_G[1][0][gb + 32 + lane] = hi; g_G[1][1][gb + 32 + lane] = lo;
    if (lane == 0) {            // Z column (64) = F itself
        bf16split(F1, hi, lo); g_G[0][0][gb + 64] = hi; g_G[0][1][gb + 64] = lo;
        bf16split(F2, hi, lo); g_G[1][0][gb + 64] = hi; g_G[1][1][gb + 64] = lo;
        g_s[warp] = s; g_d[warp] = d; g_ratio[warp] = __expf(0.8f * s);
    } else if (lane < 8) {      // zero-pad cols 65..71
        __nv_bfloat16 z = __float2bfloat16(0.f);
        g_G[0][0][gb + 64 + lane] = z; g_G[0][1][gb + 64 + lane] = z;
        g_G[1][0][gb + 64 + lane] = z; g_G[1][1][gb + 64 + lane] = z;
    }
}

// ---------------- K3: pack adjacency ----------------
__global__ void __launch_bounds__(256) k_pack(const int* __restrict__ adj) {
    const int warp = (blockIdx.x * blockDim.x + threadIdx.x) >> 5;
    const int lane = threadIdx.x & 31;
    const int base = warp * 32;
#pragma unroll 4
    for (int i = 0; i < 32; i++) {
        unsigned m = __ballot_sync(~0u, adj[(size_t)(base + i) * 32 + lane] != 0);
        if (lane == 0) g_adj[base + i] = m;
    }
}

// ---------------- K3b: predicate bitmask P[h][r][m] = (s_r + d_m >= 0) ----------------
__global__ void __launch_bounds__(256) k_pred() {
    __shared__ float ds[NN];
    const int hd = blockIdx.y;
    const int t  = threadIdx.x;
    const float4* d4 = reinterpret_cast<const float4*>(g_d + hd * NN);
    float4* ds4 = reinterpret_cast<float4*>(ds);
    for (int i = t; i < NN / 4; i += 256) ds4[i] = d4[i];
    __syncthreads();
    const int wr = t >> 5, lane = t & 31;
    const int R  = blockIdx.x * 8 + wr;
    const float s = g_s[hd * NN + R];
    unsigned* Pr = g_P + ((size_t)hd * NN + R) * 128;
#pragma unroll 4
    for (int wi = 0; wi < 128; wi++) {
        unsigned b = __ballot_sync(~0u, s + ds[wi * 32 + lane] >= 0.f);
        if (lane == 0) Pr[wi] = b;
    }
}

// ---------------- K4: binary-matrix tensor-core attention, 4-stage pipeline ----------------
// grid (32, 8): 128-row tile x head. 8 warps: rg = wid>>1 (32 rows), nh = wid&1.
// nh=0 -> cols 0..39 (5 n-tiles); nh=1 -> cols 40..71 (4 n-tiles, incl. Z col 64).
// 32-k chunks == one adjacency/predicate word. Two passes (branch), ratio-scaled.
__global__ void __launch_bounds__(256, 2) k_attn_mma() {
    __shared__ __align__(16) __nv_bfloat16 Gs[4][2][32][GW];   // [buf][sp][k][col] 36.9 KB
    __shared__ float zbuf[128];

    const int t    = threadIdx.x;
    const int lane = t & 31, wid = t >> 5;
    const int hd   = blockIdx.y;
    const int n0   = blockIdx.x * 128;
    const int rg   = wid >> 1, nh = wid & 1;
    const int R0   = rg * 32;
    const int NB   = nh * 40;
    const int NT   = nh ? 4 : 5;
    const int NQ   = nh ? 2 : 3;
    const int g    = lane >> 2, tig = lane & 3;
    const int kc   = tig * 2;

    int rows[4] = { R0 + g, R0 + 8 + g, R0 + 16 + g, R0 + 24 + g };
    const int ridx0 = hd * NN + n0;
    const unsigned* __restrict__ adjp = g_adj + (size_t)n0 * 128;
    const unsigned* __restrict__ Pp   = g_P + (size_t)ridx0 * 128;

    float acc[2][5][4];
#pragma unroll
    for (int tt = 0; tt < 2; tt++)
#pragma unroll
        for (int nt = 0; nt < 5; nt++)
#pragma unroll
            for (int q = 0; q < 4; q++) acc[tt][nt][q] = 0.f;

#pragma unroll
    for (int br = 0; br < 2; br++) {
        const __nv_bfloat16* __restrict__ Ghi = g_G[br][0] + (size_t)hd * NN * GW;
        const __nv_bfloat16* __restrict__ Glo = g_G[br][1] + (size_t)hd * NN * GW;

        // prologue: stage chunks 0..2 into bufs 0..2 (separate commit groups)
#pragma unroll
        for (int pc = 0; pc < 3; pc++) {
            const size_t mo = (size_t)pc * 32;
            for (int i = t; i < 576; i += 256) {
                int sp = i / 288, rem = i - sp * 288;
                int row = rem / 9, c16 = rem - row * 9;
                cpa16(&Gs[pc][sp][row][c16 * 8],
                      (sp ? Glo : Ghi) + (mo + row) * GW + c16 * 8);
            }
            cpcommit();
        }
        unsigned wcur[4];
#pragma unroll
        for (int i = 0; i < 4; i++) {
            unsigned aw = adjp[rows[i] * 128], pw = Pp[rows[i] * 128];
            wcur[i] = br ? (aw & ~pw) : (aw & pw);
        }

        for (int c = 0; c < 128; c++) {
            const int buf = c & 3;
            cpwait<2>();                 // tile c resident (<=2 groups outstanding)
            __syncthreads();             // all warps see tile c; done reading buf (c-1)&3
            if (c + 3 < 128) {           // stage chunk c+3 into buf (c+3)&3
                const int nb = (c + 3) & 3;
                const size_t mo = (size_t)(c + 3) * 32;
                for (int i = t; i < 576; i += 256) {
                    int sp = i / 288, rem = i - sp * 288;
                    int row = rem / 9, c16 = rem - row * 9;
                    cpa16(&Gs[nb][sp][row][c16 * 8],
                          (sp ? Glo : Ghi) + (mo + row) * GW + c16 * 8);
                }
            }
            cpcommit();                  // unconditional: uniform group counting
            unsigned wnxt[4];
            if (c + 1 < 128) {
#pragma unroll
                for (int i = 0; i < 4; i++) {
                    unsigned aw = adjp[rows[i] * 128 + c + 1];
                    unsigned pw = Pp[rows[i] * 128 + c + 1];
                    wnxt[i] = br ? (aw & ~pw) : (aw & pw);
                }
            }

#pragma unroll
            for (int kt = 0; kt < 2; kt++) {
                unsigned A[2][4];
#pragma unroll
                for (int tt = 0; tt < 2; tt++) {
                    const unsigned wa = wcur[2 * tt]     >> (kt * 16);
                    const unsigned wb = wcur[2 * tt + 1] >> (kt * 16);
                    A[tt][0] = bp2(wa, kc);
                    A[tt][1] = bp2(wb, kc);
                    A[tt][2] = bp2(wa, kc + 8);
                    A[tt][3] = bp2(wb, kc + 8);
                }
#pragma unroll
                for (int sp = 0; sp < 2; sp++) {
                    unsigned sb = (unsigned)__cvta_generic_to_shared(&Gs[buf][sp][0][0]);
                    unsigned la = sb + (kt * 16 + (lane & 15)) * (GW * 2)
                                     + ((lane & 16) ? 16 : 0);
                    unsigned b[3][4];
#pragma unroll
                    for (int q = 0; q < 3; q++)
                        if (q < NQ || !nh)           // 3 loads nh=0, 2 loads nh=1
                            if (q < (nh ? 2 : 3))
                                ldsm4t(b[q], la + (NB + q * 16) * 2);
#pragma unroll
                    for (int tt = 0; tt < 2; tt++)
#pragma unroll
                        for (int nt = 0; nt < 5; nt++)
                            if (nt < NT) {
                                const unsigned* bb = b[nt >> 1] + (nt & 1) * 2;
                                mma16816(acc[tt][nt], A[tt][0], A[tt][1],
                                         A[tt][2], A[tt][3], bb[0], bb[1]);
                            }
                }
            }
#pragma unroll
            for (int i = 0; i < 4; i++) wcur[i] = wnxt[i];
        }
        cpwait<0>();                    // drain tail groups before refilling pipeline

        // between passes: scale branch-0 partials by exp(0.8 s_row)
        if (br == 0) {
            float rat[4];
#pragma unroll
            for (int i = 0; i < 4; i++) rat[i] = g_ratio[ridx0 + rows[i]];
#pragma unroll
            for (int tt = 0; tt < 2; tt++)
#pragma unroll
                for (int nt = 0; nt < 5; nt++) {
                    acc[tt][nt][0] *= rat[2 * tt];     acc[tt][nt][1] *= rat[2 * tt];
                    acc[tt][nt][2] *= rat[2 * tt + 1]; acc[tt][nt][3] *= rat[2 * tt + 1];
                }
            __syncthreads();            // buffers reused by next pass
        }
    }

    // ---- epilogue: Z broadcast + normalize + store ----
    if (nh == 1 && tig == 0) {       // col 64 = Z lives at nh=1, nt=3, tig=0
#pragma unroll
        for (int tt = 0; tt < 2; tt++) {
            zbuf[rows[2 * tt]]     = acc[tt][3][0];
            zbuf[rows[2 * tt + 1]] = acc[tt][3][2];
        }
    }
    __syncthreads();
    float rz[4];
#pragma unroll
    for (int i = 0; i < 4; i++) rz[i] = 1.f / zbuf[rows[i]];

    float* __restrict__ hp = g_hp + ((size_t)hd * NN + n0) * OUTF;
#pragma unroll
    for (int tt = 0; tt < 2; tt++)
#pragma unroll
        for (int nt = 0; nt < 5; nt++) {
            const int col0 = NB + nt * 8;
            if (nt < NT && col0 < 64) {
                const int col = col0 + kc;
                float2 o0 = make_float2(acc[tt][nt][0] * rz[2 * tt],
                                        acc[tt][nt][1] * rz[2 * tt]);
                float2 o1 = make_float2(acc[tt][nt][2] * rz[2 * tt + 1],
                                        acc[tt][nt][3] * rz[2 * tt + 1]);
                *(float2*)(hp + (size_t)rows[2 * tt] * OUTF + col)     = o0;
                *(float2*)(hp + (size_t)rows[2 * tt + 1] * OUTF + col) = o1;
            }
        }
}

// ---------------- K5: mean over heads + ELU ----------------
__global__ void __launch_bounds__(256) k_final(float* __restrict__ out) {
    const int i = blockIdx.x * 256 + threadIdx.x;
    float s = 0.f;
#pragma unroll
    for (int hd = 0; hd < H; hd++) s += g_hp[(size_t)hd * NN * OUTF + i];
    s *= (1.f / H);
    out[i] = (s > 0.f) ? s : (__expf(s) - 1.f);
}

// ---------------- launch ----------------
extern "C" void kernel_launch(void* const* d_in, const int* in_sizes, int n_in,
                              void* d_out, int out_size) {
    const float* x   = (const float*)d_in[0];
    const int*   adj = (const int*)  d_in[1];
    const float* W   = (const float*)d_in[2];
    const float* a   = (const float*)d_in[3];
    float* out = (float*)d_out;

    k_gemm    <<<128, 512>>>(x, W);
    k_attvec  <<<H * NN / 8, 256>>>(a);
    k_pack    <<<2048, 256>>>(adj);
    k_pred    <<<dim3(NN / 8, H), 256>>>();
    k_attn_mma<<<dim3(32, 8), 256>>>();
    k_final   <<<NN * OUTF / 256, 256>>>(out);
}

// round 16
// speedup vs baseline: 3.3228x; 1.1016x over previous
#include <cuda_runtime.h>
#include <cuda_bf16.h>

#define NN   4096
#define INF  256
#define OUTF 64
#define H    8
#define GW   72          // G row width (bf16): 64 h + 1 Z + 7 pad (144B stride, conflict-free)

// ---------------- device scratch ----------------
__device__ float  g_h [H*NN*OUTF];              // projected features (8 MB)
__device__ float  g_hp[H*NN*OUTF];              // per-head attention output
__device__ float  g_s[H*NN], g_d[H*NN], g_ratio[H*NN];
__device__ __nv_bfloat16 g_G[2][2][H*NN*GW];    // [branch][hi/lo] G = diag(F)*[h|1|0]
__device__ unsigned g_adj[NN*(NN/32)];          // packed adjacency (2 MB)
__device__ unsigned g_P[H*NN*(NN/32)];          // predicate bitmask s_r+d_m>=0 (16 MB)

// ---------------- helpers ----------------
__device__ __forceinline__ void cpa16(void* dst, const void* src) {
    unsigned ds = (unsigned)__cvta_generic_to_shared(dst);
    asm volatile("cp.async.ca.shared.global [%0], [%1], 16;" :: "r"(ds), "l"(src));
}
__device__ __forceinline__ void cpcommit() { asm volatile("cp.async.commit_group;"); }
template <int N>
__device__ __forceinline__ void cpwait() {
    asm volatile("cp.async.wait_group %0;" :: "n"(N));
}
__device__ __forceinline__ void ldsm4t(unsigned* r, unsigned addr) {
    asm volatile("ldmatrix.sync.aligned.m8n8.x4.trans.shared.b16 {%0,%1,%2,%3}, [%4];"
        : "=r"(r[0]), "=r"(r[1]), "=r"(r[2]), "=r"(r[3]) : "r"(addr));
}
__device__ __forceinline__ void ldsm2t(unsigned* r, unsigned addr) {
    asm volatile("ldmatrix.sync.aligned.m8n8.x2.trans.shared.b16 {%0,%1}, [%2];"
        : "=r"(r[0]), "=r"(r[1]) : "r"(addr));
}
__device__ __forceinline__ void mma16816(float* c, unsigned a0, unsigned a1,
                                         unsigned a2, unsigned a3,
                                         unsigned b0, unsigned b1) {
    asm volatile("mma.sync.aligned.m16n8k16.row.col.f32.bf16.bf16.f32 "
        "{%0,%1,%2,%3}, {%4,%5,%6,%7}, {%8,%9}, {%0,%1,%2,%3};"
        : "+f"(c[0]), "+f"(c[1]), "+f"(c[2]), "+f"(c[3])
        : "r"(a0), "r"(a1), "r"(a2), "r"(a3), "r"(b0), "r"(b1));
}
// two mask bits (k, k+1) -> packed {bf16(1|0), bf16(1|0)}
__device__ __forceinline__ unsigned bp2(unsigned w, int k) {
    return ((w >> k) & 1u) * 0x3F80u + ((w >> (k + 1)) & 1u) * 0x3F800000u;
}
__device__ __forceinline__ void bf16split(float x, __nv_bfloat16& hi, __nv_bfloat16& lo) {
    hi = __float2bfloat16(x);
    lo = __float2bfloat16(x - __bfloat162float(hi));
}

// ---------------- K1: h = x @ W ----------------
__global__ void __launch_bounds__(512) k_gemm(const float* __restrict__ x,
                                              const float* __restrict__ W) {
    __shared__ float4 xs[32][64];
    const int t  = threadIdx.x;
    const int n0 = blockIdx.x * 32;
    const float4* x4 = reinterpret_cast<const float4*>(x) + (size_t)n0 * 64;
    for (int i = t; i < 32 * 64; i += 512) xs[i >> 6][i & 63] = x4[(i >> 6) * 64 + (i & 63)];
    __syncthreads();

    const int hd = t >> 6, o = t & 63;
    const float* Wp = W + hd * INF * OUTF + o;
    float acc[32];
#pragma unroll
    for (int r = 0; r < 32; r++) acc[r] = 0.f;
    for (int k4 = 0; k4 < 64; k4++) {
        float w0 = Wp[(4 * k4 + 0) * OUTF];
        float w1 = Wp[(4 * k4 + 1) * OUTF];
        float w2 = Wp[(4 * k4 + 2) * OUTF];
        float w3 = Wp[(4 * k4 + 3) * OUTF];
#pragma unroll
        for (int r = 0; r < 32; r++) {
            float4 xv = xs[r][k4];
            acc[r] += xv.x * w0 + xv.y * w1 + xv.z * w2 + xv.w * w3;
        }
    }
#pragma unroll
    for (int r = 0; r < 32; r++)
        g_h[((size_t)hd * NN + n0 + r) * OUTF + o] = acc[r];
}

// ---------------- K2: attention vectors + G matrices (bf16 hi/lo) ----------------
__global__ void __launch_bounds__(256) k_attvec(const float* __restrict__ a) {
    const int warp = (blockIdx.x * blockDim.x + threadIdx.x) >> 5;
    const int lane = threadIdx.x & 31;
    if (warp >= H * NN) return;
    const int hd = warp >> 12;
    const float* hv = g_h + (size_t)warp * OUTF;
    const float* ap = a + hd * (2 * OUTF);
    float v0 = hv[lane], v1 = hv[32 + lane];
    float s = v0 * ap[lane]      + v1 * ap[32 + lane];
    float d = v0 * ap[64 + lane] + v1 * ap[96 + lane];
#pragma unroll
    for (int off = 16; off; off >>= 1) {
        s += __shfl_xor_sync(~0u, s, off);
        d += __shfl_xor_sync(~0u, d, off);
    }
    const float F1 = __expf(d), F2 = __expf(0.2f * d);
    const size_t gb = (size_t)warp * GW;
    __nv_bfloat16 hi, lo;
    bf16split(F1 * v0, hi, lo); g_G[0][0][gb + lane] = hi;      g_G[0][1][gb + lane] = lo;
    bf16split(F1 * v1, hi, lo); g_G[0][0][gb + 32 + lane] = hi; g_G[0][1][gb + 32 + lane] = lo;
    bf16split(F2 * v0, hi, lo); g_G[1][0][gb + lane] = hi;      g_G[1][1][gb + lane] = lo;
    bf16split(F2 * v1, hi, lo); g_G[1][0][gb + 32 + lane] = hi; g_G[1][1][gb + 32 + lane] = lo;
    if (lane == 0) {            // Z column (64) = F itself
        bf16split(F1, hi, lo); g_G[0][0][gb + 64] = hi; g_G[0][1][gb + 64] = lo;
        bf16split(F2, hi, lo); g_G[1][0][gb + 64] = hi; g_G[1][1][gb + 64] = lo;
        g_s[warp] = s; g_d[warp] = d; g_ratio[warp] = __expf(0.8f * s);
    } else if (lane < 8) {      // zero-pad cols 65..71
        __nv_bfloat16 z = __float2bfloat16(0.f);
        g_G[0][0][gb + 64 + lane] = z; g_G[0][1][gb + 64 + lane] = z;
        g_G[1][0][gb + 64 + lane] = z; g_G[1][1][gb + 64 + lane] = z;
    }
}

// ---------------- K3: pack adjacency ----------------
__global__ void __launch_bounds__(256) k_pack(const int* __restrict__ adj) {
    const int warp = (blockIdx.x * blockDim.x + threadIdx.x) >> 5;
    const int lane = threadIdx.x & 31;
    const int base = warp * 32;
#pragma unroll 4
    for (int i = 0; i < 32; i++) {
        unsigned m = __ballot_sync(~0u, adj[(size_t)(base + i) * 32 + lane] != 0);
        if (lane == 0) g_adj[base + i] = m;
    }
}

// ---------------- K3b: predicate bitmask P[h][r][m] = (s_r + d_m >= 0) ----------------
__global__ void __launch_bounds__(256) k_pred() {
    __shared__ float ds[NN];
    const int hd = blockIdx.y;
    const int t  = threadIdx.x;
    const float4* d4 = reinterpret_cast<const float4*>(g_d + hd * NN);
    float4* ds4 = reinterpret_cast<float4*>(ds);
    for (int i = t; i < NN / 4; i += 256) ds4[i] = d4[i];
    __syncthreads();
    const int wr = t >> 5, lane = t & 31;
    const int R  = blockIdx.x * 8 + wr;
    const float s = g_s[hd * NN + R];
    unsigned* Pr = g_P + ((size_t)hd * NN + R) * 128;
#pragma unroll 4
    for (int wi = 0; wi < 128; wi++) {
        unsigned b = __ballot_sync(~0u, s + ds[wi * 32 + lane] >= 0.f);
        if (lane == 0) Pr[wi] = b;
    }
}

// ---------------- K4: binary-matrix tensor-core attention (balanced warps) ----------
// grid (32, 8): 128-row tile x head. 8 warps, warp w -> rows [w*16, w*16+16),
// ALL 9 n-tiles (72 cols incl. Z at 64). 32-k chunks = 1 mask word. Two branch
// passes share one accumulator via the exp(0.8 s) ratio trick.
__global__ void __launch_bounds__(256, 2) k_attn_mma() {
    __shared__ __align__(16) __nv_bfloat16 Gs[4][2][32][GW];   // [buf][sp][k][col] 36.9 KB

    const int t    = threadIdx.x;
    const int lane = t & 31, wid = t >> 5;
    const int hd   = blockIdx.y;
    const int n0   = blockIdx.x * 128;
    const int R0   = wid * 16;
    const int g    = lane >> 2, tig = lane & 3;
    const int kc   = tig * 2;

    const int r0 = R0 + g, r1 = R0 + 8 + g;           // this thread's two rows
    const int ridx0 = hd * NN + n0;
    const unsigned* __restrict__ adj0 = g_adj + (size_t)(n0 + r0) * 128;
    const unsigned* __restrict__ adj1 = g_adj + (size_t)(n0 + r1) * 128;
    const unsigned* __restrict__ P0   = g_P + ((size_t)ridx0 + r0) * 128;
    const unsigned* __restrict__ P1   = g_P + ((size_t)ridx0 + r1) * 128;

    float acc[9][4];
#pragma unroll
    for (int nt = 0; nt < 9; nt++)
#pragma unroll
        for (int q = 0; q < 4; q++) acc[nt][q] = 0.f;

#pragma unroll
    for (int br = 0; br < 2; br++) {
        const __nv_bfloat16* __restrict__ Ghi = g_G[br][0] + (size_t)hd * NN * GW;
        const __nv_bfloat16* __restrict__ Glo = g_G[br][1] + (size_t)hd * NN * GW;

        // prologue: stage chunks 0..2 (2 sp x 32 rows x 9 x 16B = 576 cpa each)
#pragma unroll
        for (int pc = 0; pc < 3; pc++) {
            const size_t mo = (size_t)pc * 32;
            for (int i = t; i < 576; i += 256) {
                int sp = i / 288, rem = i - sp * 288;
                int row = rem / 9, c16 = rem - row * 9;
                cpa16(&Gs[pc][sp][row][c16 * 8],
                      (sp ? Glo : Ghi) + (mo + row) * GW + c16 * 8);
            }
            cpcommit();
        }
        unsigned w0, w1;
        {
            unsigned a0 = adj0[0], p0 = P0[0], a1 = adj1[0], p1 = P1[0];
            w0 = br ? (a0 & ~p0) : (a0 & p0);
            w1 = br ? (a1 & ~p1) : (a1 & p1);
        }

        for (int c = 0; c < 128; c++) {
            const int buf = c & 3;
            cpwait<2>();                 // tile c resident
            __syncthreads();
            if (c + 3 < 128) {           // stage chunk c+3
                const int nb = (c + 3) & 3;
                const size_t mo = (size_t)(c + 3) * 32;
                for (int i = t; i < 576; i += 256) {
                    int sp = i / 288, rem = i - sp * 288;
                    int row = rem / 9, c16 = rem - row * 9;
                    cpa16(&Gs[nb][sp][row][c16 * 8],
                          (sp ? Glo : Ghi) + (mo + row) * GW + c16 * 8);
                }
            }
            cpcommit();                  // uniform group counting
            unsigned n0w = 0, n1w = 0;
            if (c + 1 < 128) {
                unsigned a0 = adj0[c + 1], p0 = P0[c + 1];
                unsigned a1 = adj1[c + 1], p1 = P1[c + 1];
                n0w = br ? (a0 & ~p0) : (a0 & p0);
                n1w = br ? (a1 & ~p1) : (a1 & p1);
            }

#pragma unroll
            for (int kt = 0; kt < 2; kt++) {
                const unsigned wa = w0 >> (kt * 16);
                const unsigned wb = w1 >> (kt * 16);
                unsigned A0 = bp2(wa, kc), A1 = bp2(wb, kc);
                unsigned A2 = bp2(wa, kc + 8), A3 = bp2(wb, kc + 8);
#pragma unroll
                for (int sp = 0; sp < 2; sp++) {
                    unsigned sb = (unsigned)__cvta_generic_to_shared(&Gs[buf][sp][0][0]);
                    unsigned la = sb + (kt * 16 + (lane & 15)) * (GW * 2)
                                     + ((lane & 16) ? 16 : 0);
                    unsigned b[18];
#pragma unroll
                    for (int q = 0; q < 4; q++)
                        ldsm4t(b + q * 4, la + (q * 16) * 2);
                    ldsm2t(b + 16, la + 64 * 2);           // Z tile (cols 64..71)
#pragma unroll
                    for (int nt = 0; nt < 9; nt++)
                        mma16816(acc[nt], A0, A1, A2, A3, b[nt * 2], b[nt * 2 + 1]);
                }
            }
            w0 = n0w; w1 = n1w;
        }
        cpwait<0>();                    // drain tail before refilling pipeline

        // between passes: scale branch-0 partials by exp(0.8 s_row)
        if (br == 0) {
            const float ra = g_ratio[ridx0 + r0];
            const float rb = g_ratio[ridx0 + r1];
#pragma unroll
            for (int nt = 0; nt < 9; nt++) {
                acc[nt][0] *= ra; acc[nt][1] *= ra;
                acc[nt][2] *= rb; acc[nt][3] *= rb;
            }
            __syncthreads();            // buffers reused by next pass
        }
    }

    // ---- epilogue: Z via intra-quad shuffle, normalize, store ----
    const float z0 = __shfl_sync(0xFFFFFFFFu, acc[8][0], lane & 28);
    const float z1 = __shfl_sync(0xFFFFFFFFu, acc[8][2], lane & 28);
    const float rz0 = 1.f / z0, rz1 = 1.f / z1;

    float* __restrict__ hp = g_hp + ((size_t)hd * NN + n0) * OUTF;
#pragma unroll
    for (int nt = 0; nt < 8; nt++) {
        const int col = nt * 8 + kc;
        *(float2*)(hp + (size_t)r0 * OUTF + col) =
            make_float2(acc[nt][0] * rz0, acc[nt][1] * rz0);
        *(float2*)(hp + (size_t)r1 * OUTF + col) =
            make_float2(acc[nt][2] * rz1, acc[nt][3] * rz1);
    }
}

// ---------------- K5: mean over heads + ELU ----------------
__global__ void __launch_bounds__(256) k_final(float* __restrict__ out) {
    const int i = blockIdx.x * 256 + threadIdx.x;
    float s = 0.f;
#pragma unroll
    for (int hd = 0; hd < H; hd++) s += g_hp[(size_t)hd * NN * OUTF + i];
    s *= (1.f / H);
    out[i] = (s > 0.f) ? s : (__expf(s) - 1.f);
}

// ---------------- launch ----------------
extern "C" void kernel_launch(void* const* d_in, const int* in_sizes, int n_in,
                              void* d_out, int out_size) {
    const float* x   = (const float*)d_in[0];
    const int*   adj = (const int*)  d_in[1];
    const float* W   = (const float*)d_in[2];
    const float* a   = (const float*)d_in[3];
    float* out = (float*)d_out;

    k_gemm    <<<128, 512>>>(x, W);
    k_attvec  <<<H * NN / 8, 256>>>(a);
    k_pack    <<<2048, 256>>>(adj);
    k_pred    <<<dim3(NN / 8, H), 256>>>();
    k_attn_mma<<<dim3(32, 8), 256>>>();
    k_final   <<<NN * OUTF / 256, 256>>>(out);
}